// round 13
// baseline (speedup 1.0000x reference)
#include <cuda_runtime.h>
#include <cuda_fp16.h>
#include <cuda_bf16.h>
#include <cstdint>

#define BB 16
#define N1 4096
#define N2 1024
#define C1 128
#define C2 256
#define DIN 384
#define DOUT 256
#define NQ (BB * N1)

// ---------------- device scratch ----------------
__device__ __align__(16) __half g_X[(size_t)NQ * DIN];
__device__ __align__(16) __half g_H[(size_t)NQ * DOUT];
__device__ __align__(16) __half g_W1T[DOUT * DIN];
__device__ __align__(16) __half g_W2T[DOUT * DOUT];

// ---------------- PTX helpers (portable, OK on compute_103) ----------------
__device__ __forceinline__ uint32_t smem_u32(const void* p) {
    uint32_t a;
    asm("{ .reg .u64 t; cvta.to.shared.u64 t, %1; cvt.u32.u64 %0, t; }" : "=r"(a) : "l"(p));
    return a;
}
#define CP_ASYNC16(dst, src) \
    asm volatile("cp.async.cg.shared.global [%0], [%1], 16;" :: "r"(dst), "l"(src))
#define CP_COMMIT() asm volatile("cp.async.commit_group;" ::: "memory")
#define CP_WAIT(n)  asm volatile("cp.async.wait_group %0;" :: "n"(n) : "memory")

__device__ __forceinline__ void ldmatrix_x4(uint32_t* r, uint32_t addr) {
    asm volatile("ldmatrix.sync.aligned.m8n8.x4.shared.b16 {%0,%1,%2,%3}, [%4];"
                 : "=r"(r[0]), "=r"(r[1]), "=r"(r[2]), "=r"(r[3]) : "r"(addr));
}
__device__ __forceinline__ void mma16816(float* d, const uint32_t* a, const uint32_t* b) {
    asm volatile(
        "mma.sync.aligned.m16n8k16.row.col.f32.f16.f16.f32 "
        "{%0,%1,%2,%3}, {%4,%5,%6,%7}, {%8,%9}, {%0,%1,%2,%3};"
        : "+f"(d[0]), "+f"(d[1]), "+f"(d[2]), "+f"(d[3])
        : "r"(a[0]), "r"(a[1]), "r"(a[2]), "r"(a[3]), "r"(b[0]), "r"(b[1]));
}
#define SWZ(bo) ((bo) ^ (((bo) >> 3) & 0x70))

// ---------------------------------------------------------------------------
// Kernel 0: W1/W2 transpose -> fp16 (tiny, 3 blocks)
// ---------------------------------------------------------------------------
#define PREPW_ELEMS (DIN * DOUT + DOUT * DOUT)

__global__ void prep_w(const float* __restrict__ W1, const float* __restrict__ W2) {
    for (int i = blockIdx.x * 256 + threadIdx.x; i < PREPW_ELEMS; i += 3 * 256 * 86) {
        // grid-stride not needed; grid covers exactly
    }
    int i = blockIdx.x * 256 + threadIdx.x;
    for (; i < PREPW_ELEMS; i += gridDim.x * 256) {
        if (i < DIN * DOUT) {
            int k = i / DOUT, n = i % DOUT;
            g_W1T[n * DIN + k] = __float2half(W1[i]);
        } else {
            int j = i - DIN * DOUT;
            int k = j / DOUT, n = j % DOUT;
            g_W2T[n * DOUT + k] = __float2half(W2[j]);
        }
    }
}

// ---------------------------------------------------------------------------
// Kernel A: fused 3-NN + interpolation + concat. One block = 64 queries.
// knn: R8-proven (val-key select, exact reference-form winner distances).
// interp: fp32 gather with COALESCED lane indexing (lane, lane+32) -> X fp16.
// ---------------------------------------------------------------------------
__global__ __launch_bounds__(256) void knn_interp_kernel(
    const float* __restrict__ xyz1, const float* __restrict__ xyz2,
    const float* __restrict__ feat1, const float* __restrict__ feat2) {
    __shared__ float4 pts[N2];
    __shared__ int   sidx[64 * 3];
    __shared__ float swt[64 * 3];

    const int qb = blockIdx.x * 64;
    const int b = qb >> 12;
    const float* x2 = xyz2 + (size_t)b * N2 * 3;
    for (int j = threadIdx.x; j < N2; j += 256) {
        float x = x2[3 * j], y = x2[3 * j + 1], z = x2[3 * j + 2];
        pts[j] = make_float4(x, y, z, x * x + y * y + z * z);
    }
    __syncthreads();

    // ---- phase 1: knn ----
    {
        const int lq = threadIdx.x >> 2;
        const int q = qb + lq;
        const int sub = threadIdx.x & 3;
        const float qx = xyz1[3 * q], qy = xyz1[3 * q + 1], qz = xyz1[3 * q + 2];
        const float ax = -2.0f * qx, ay = -2.0f * qy, az = -2.0f * qz;

        float b0 = 3.4e38f, b1 = 3.4e38f, b2 = 3.4e38f;
        int i0 = 0, i1 = 0, i2 = 0;
#pragma unroll 8
        for (int i = 0; i < 256; i++) {
            const int j = sub + 4 * i;
            float4 p = pts[j];
            float v = fmaf(ax, p.x, fmaf(ay, p.y, fmaf(az, p.z, p.w)));
            if (v < b2) {
                if (v < b1) {
                    if (v < b0) { b2 = b1; i2 = i1; b1 = b0; i1 = i0; b0 = v; i0 = j; }
                    else        { b2 = b1; i2 = i1; b1 = v; i1 = j; }
                } else { b2 = v; i2 = j; }
            }
        }
#pragma unroll
        for (int dlt = 1; dlt <= 2; dlt <<= 1) {
            float c0 = __shfl_xor_sync(0xffffffffu, b0, dlt);
            float c1 = __shfl_xor_sync(0xffffffffu, b1, dlt);
            float c2 = __shfl_xor_sync(0xffffffffu, b2, dlt);
            int k0 = __shfl_xor_sync(0xffffffffu, i0, dlt);
            int k1 = __shfl_xor_sync(0xffffffffu, i1, dlt);
            int k2 = __shfl_xor_sync(0xffffffffu, i2, dlt);
            if (c0 < b0) {   // full triple swap keeps b-triple sorted
                float tf; int ti;
                tf = b0; b0 = c0; c0 = tf; ti = i0; i0 = k0; k0 = ti;
                tf = b1; b1 = c1; c1 = tf; ti = i1; i1 = k1; k1 = ti;
                tf = b2; b2 = c2; c2 = tf; ti = i2; i2 = k2; k2 = ti;
            }
            if (c0 < b1) {
                if (b1 < c1) { b2 = b1; i2 = i1; } else { b2 = c1; i2 = k1; }
                b1 = c0; i1 = k0;
            } else if (c0 < b2) { b2 = c0; i2 = k0; }
            (void)c2; (void)k2;
        }
        if (sub == 0) {
            float4 p0 = pts[i0], p1 = pts[i1], p2 = pts[i2];
            float dx, dy, dz;
            dx = qx - p0.x; dy = qy - p0.y; dz = qz - p0.z;
            float d0 = fmaxf(dx * dx + dy * dy + dz * dz, 1e-10f);
            dx = qx - p1.x; dy = qy - p1.y; dz = qz - p1.z;
            float d1 = fmaxf(dx * dx + dy * dy + dz * dz, 1e-10f);
            dx = qx - p2.x; dy = qy - p2.y; dz = qz - p2.z;
            float d2 = fmaxf(dx * dx + dy * dy + dz * dz, 1e-10f);
            float w0 = 1.0f / d0, w1 = 1.0f / d1, w2 = 1.0f / d2;
            float inv = 1.0f / (w0 + w1 + w2);
            sidx[lq * 3] = i0; sidx[lq * 3 + 1] = i1; sidx[lq * 3 + 2] = i2;
            swt[lq * 3] = w0 * inv; swt[lq * 3 + 1] = w1 * inv; swt[lq * 3 + 2] = w2 * inv;
        }
    }
    __syncthreads();

    // ---- phase 2: fp32 gather (coalesced) + concat (warp/query, 8 iters) ----
    const int wq = threadIdx.x >> 5;
    const int lane = threadIdx.x & 31;
    const float* f2 = feat2 + (size_t)b * N2 * C2;
#pragma unroll
    for (int it = 0; it < 8; it++) {
        const int lq = it * 8 + wq;
        const int q = qb + lq;
        const int i0 = sidx[lq * 3], i1 = sidx[lq * 3 + 1], i2 = sidx[lq * 3 + 2];
        const float w0 = swt[lq * 3], w1 = swt[lq * 3 + 1], w2 = swt[lq * 3 + 2];

        const float4* r0 = (const float4*)(f2 + (size_t)i0 * C2);
        const float4* r1 = (const float4*)(f2 + (size_t)i1 * C2);
        const float4* r2 = (const float4*)(f2 + (size_t)i2 * C2);
        __half* x = g_X + (size_t)q * DIN;

        // two coalesced rounds: float4 index c = lane, then c = lane + 32
#pragma unroll
        for (int seg = 0; seg < 2; seg++) {
            const int c = lane + seg * 32;
            float4 a = r0[c], d = r1[c], e = r2[c];
            float ox = w0 * a.x + w1 * d.x + w2 * e.x;
            float oy = w0 * a.y + w1 * d.y + w2 * e.y;
            float oz = w0 * a.z + w1 * d.z + w2 * e.z;
            float ow = w0 * a.w + w1 * d.w + w2 * e.w;
            uint2 o;
            __half2 p0 = __floats2half2_rn(ox, oy);
            __half2 p1 = __floats2half2_rn(oz, ow);
            o.x = *(const uint32_t*)&p0;
            o.y = *(const uint32_t*)&p1;
            *(uint2*)(x + 4 * c) = o;   // cols [4c, 4c+4)
        }

        float4 f = ((const float4*)(feat1 + (size_t)q * C1))[lane];
        __half2 f0 = __floats2half2_rn(f.x, f.y);
        __half2 f1h = __floats2half2_rn(f.z, f.w);
        *(__half2*)(x + C2 + lane * 4) = f0;
        *(__half2*)(x + C2 + lane * 4 + 2) = f1h;
    }
}

// ---------------------------------------------------------------------------
// HGEMM (R8, proven): CTA tile 128x128, BK=64, 256 threads, 64x32 warp tiles,
// 3-stage cp.async pipeline, one __syncthreads per chunk.
// ---------------------------------------------------------------------------
#define HGEMM_SMEM (3 * 32768)

template<int K, bool WRITE_H>
__global__ __launch_bounds__(256, 2) void hgemm(
    const __half* __restrict__ A, const __half* __restrict__ Bt,
    const float* __restrict__ bias,
    __half* __restrict__ outH, float* __restrict__ outF) {
    constexpr int NC = K / 64;
    extern __shared__ char smem[];
    const uint32_t sb = smem_u32(smem);
    const int tid = threadIdx.x;
    const int w = tid >> 5, lane = tid & 31;
    const int wy = w >> 2, wx = w & 3;
    const int mblk = blockIdx.y * 128, nblk = blockIdx.x * 128;

    const char* Abase = (const char*)(A + (size_t)mblk * K);
    const char* Bbase = (const char*)(Bt + (size_t)nblk * K);
    const int row_l = tid >> 3;
    const int ch_l = tid & 7;

    float acc[4][4][4];
#pragma unroll
    for (int i = 0; i < 4; i++)
#pragma unroll
        for (int j = 0; j < 4; j++)
#pragma unroll
            for (int k = 0; k < 4; k++) acc[i][j][k] = 0.0f;

    auto issue = [&](int c) {
        const uint32_t base = sb + (uint32_t)(c % 3) * 32768u;
        const char* ag = Abase + (size_t)c * 128;
        const char* bg = Bbase + (size_t)c * 128;
#pragma unroll
        for (int rr = 0; rr < 4; rr++) {
            const int row = row_l + rr * 32;
            const uint32_t off = (uint32_t)(row * 128 + ch_l * 16);
            const uint32_t d = base + SWZ(off);
            CP_ASYNC16(d, ag + (size_t)row * (K * 2) + ch_l * 16);
            CP_ASYNC16(d + 16384, bg + (size_t)row * (K * 2) + ch_l * 16);
        }
        CP_COMMIT();
    };

    issue(0);
    issue(1);
#pragma unroll
    for (int c = 0; c < NC; c++) {
        if (c + 1 < NC) { CP_WAIT(1); } else { CP_WAIT(0); }
        __syncthreads();
        const uint32_t abase = sb + (uint32_t)(c % 3) * 32768u;
        const uint32_t bbase = abase + 16384u;
#pragma unroll
        for (int ks = 0; ks < 4; ks++) {
            uint32_t af[4][4];
#pragma unroll
            for (int mt = 0; mt < 4; mt++) {
                const int row = wy * 64 + mt * 16 + ((lane >> 3) & 1) * 8 + (lane & 7);
                const int ch = ks * 2 + (lane >> 4);
                ldmatrix_x4(af[mt], abase + SWZ((uint32_t)(row * 128 + ch * 16)));
            }
            uint32_t bf[4][2];
#pragma unroll
            for (int p = 0; p < 2; p++) {
                const int t = lane >> 3;
                const int nrow = wx * 32 + (2 * p + (t >> 1)) * 8 + (lane & 7);
                const int ch = ks * 2 + (t & 1);
                uint32_t r[4];
                ldmatrix_x4(r, bbase + SWZ((uint32_t)(nrow * 128 + ch * 16)));
                bf[2 * p][0] = r[0]; bf[2 * p][1] = r[1];
                bf[2 * p + 1][0] = r[2]; bf[2 * p + 1][1] = r[3];
            }
#pragma unroll
            for (int mt = 0; mt < 4; mt++)
#pragma unroll
                for (int nt = 0; nt < 4; nt++)
                    mma16816(acc[mt][nt], af[mt], bf[nt]);
        }
        if (c + 2 < NC) issue(c + 2);
    }

#pragma unroll
    for (int mt = 0; mt < 4; mt++) {
#pragma unroll
        for (int nt = 0; nt < 4; nt++) {
            const int row0 = mblk + wy * 64 + mt * 16 + (lane >> 2);
            const int col = nblk + wx * 32 + nt * 8 + 2 * (lane & 3);
            const float bz0 = bias[col], bz1 = bias[col + 1];
            float v00 = fmaxf(acc[mt][nt][0] + bz0, 0.0f);
            float v01 = fmaxf(acc[mt][nt][1] + bz1, 0.0f);
            float v10 = fmaxf(acc[mt][nt][2] + bz0, 0.0f);
            float v11 = fmaxf(acc[mt][nt][3] + bz1, 0.0f);
            if constexpr (WRITE_H) {
                *(__half2*)(outH + (size_t)row0 * 256 + col) = __floats2half2_rn(v00, v01);
                *(__half2*)(outH + (size_t)(row0 + 8) * 256 + col) = __floats2half2_rn(v10, v11);
            } else {
                float2 o0; o0.x = v00; o0.y = v01;
                float2 o1; o1.x = v10; o1.y = v11;
                *(float2*)(outF + (size_t)row0 * 256 + col) = o0;
                *(float2*)(outF + (size_t)(row0 + 8) * 256 + col) = o1;
            }
        }
    }
}

// ---------------------------------------------------------------------------
extern "C" void kernel_launch(void* const* d_in, const int* in_sizes, int n_in,
                              void* d_out, int out_size) {
    const float* xyz1  = (const float*)d_in[0];
    const float* feat1 = (const float*)d_in[1];
    const float* xyz2  = (const float*)d_in[2];
    const float* feat2 = (const float*)d_in[3];
    const float* W1    = (const float*)d_in[4];
    const float* b1    = (const float*)d_in[5];
    const float* W2    = (const float*)d_in[6];
    const float* b2    = (const float*)d_in[7];
    float* out = (float*)d_out;

    __half *X, *H, *W1T, *W2T;
    cudaGetSymbolAddress((void**)&X, g_X);
    cudaGetSymbolAddress((void**)&H, g_H);
    cudaGetSymbolAddress((void**)&W1T, g_W1T);
    cudaGetSymbolAddress((void**)&W2T, g_W2T);

    cudaFuncSetAttribute((const void*)hgemm<DIN, true>,
                         cudaFuncAttributeMaxDynamicSharedMemorySize, HGEMM_SMEM);
    cudaFuncSetAttribute((const void*)hgemm<DOUT, false>,
                         cudaFuncAttributeMaxDynamicSharedMemorySize, HGEMM_SMEM);

    prep_w<<<3, 256>>>(W1, W2);
    knn_interp_kernel<<<NQ / 64, 256>>>(xyz1, xyz2, feat1, feat2);

    dim3 grid(DOUT / 128, NQ / 128);
    hgemm<DIN, true><<<grid, 256, HGEMM_SMEM>>>(X, W1T, b1, H, nullptr);
    hgemm<DOUT, false><<<grid, 256, HGEMM_SMEM>>>(H, W2T, b2, nullptr, out);
}

// round 14
// speedup vs baseline: 1.9327x; 1.9327x over previous
#include <cuda_runtime.h>
#include <cuda_fp16.h>
#include <cuda_bf16.h>
#include <cstdint>

#define BB 16
#define N1 4096
#define N2 1024
#define C1 128
#define C2 256
#define DIN 384
#define DOUT 256
#define NQ (BB * N1)

// ---------------- device scratch ----------------
__device__ __align__(16) __half g_X[(size_t)NQ * DIN];
__device__ __align__(16) __half g_H[(size_t)NQ * DOUT];
__device__ __align__(16) __half g_W1T[DOUT * DIN];
__device__ __align__(16) __half g_W2T[DOUT * DOUT];
__device__ __align__(16) __half g_feat2h[(size_t)BB * N2 * C2];

// ---------------- PTX helpers (portable, OK on compute_103) ----------------
__device__ __forceinline__ uint32_t smem_u32(const void* p) {
    uint32_t a;
    asm("{ .reg .u64 t; cvta.to.shared.u64 t, %1; cvt.u32.u64 %0, t; }" : "=r"(a) : "l"(p));
    return a;
}
#define CP_ASYNC16(dst, src) \
    asm volatile("cp.async.cg.shared.global [%0], [%1], 16;" :: "r"(dst), "l"(src))
#define CP_COMMIT() asm volatile("cp.async.commit_group;" ::: "memory")
#define CP_WAIT(n)  asm volatile("cp.async.wait_group %0;" :: "n"(n) : "memory")

__device__ __forceinline__ void ldmatrix_x4(uint32_t* r, uint32_t addr) {
    asm volatile("ldmatrix.sync.aligned.m8n8.x4.shared.b16 {%0,%1,%2,%3}, [%4];"
                 : "=r"(r[0]), "=r"(r[1]), "=r"(r[2]), "=r"(r[3]) : "r"(addr));
}
__device__ __forceinline__ void mma16816(float* d, const uint32_t* a, const uint32_t* b) {
    asm volatile(
        "mma.sync.aligned.m16n8k16.row.col.f32.f16.f16.f32 "
        "{%0,%1,%2,%3}, {%4,%5,%6,%7}, {%8,%9}, {%0,%1,%2,%3};"
        : "+f"(d[0]), "+f"(d[1]), "+f"(d[2]), "+f"(d[3])
        : "r"(a[0]), "r"(a[1]), "r"(a[2]), "r"(a[3]), "r"(b[0]), "r"(b[1]));
}
#define SWZ(bo) ((bo) ^ (((bo) >> 3) & 0x70))

// ---------------------------------------------------------------------------
// Kernel A (R8, proven): fused 3-NN + interpolation + concat. 64 queries/blk.
// knn: 4 threads/query, val-key selection (|p|^2 - 2 q.p), winners' distances
// recomputed in the exact reference (x1-x2)^2 form.
// interp: fp16 gather (1 uint4/lane per neighbor row), warp per query.
// ---------------------------------------------------------------------------
__global__ __launch_bounds__(256) void knn_interp_kernel(
    const float* __restrict__ xyz1, const float* __restrict__ xyz2,
    const float* __restrict__ feat1) {
    __shared__ float4 pts[N2];
    __shared__ int   sidx[64 * 3];
    __shared__ float swt[64 * 3];

    const int qb = blockIdx.x * 64;
    const int b = qb >> 12;
    const float* x2 = xyz2 + (size_t)b * N2 * 3;
    for (int j = threadIdx.x; j < N2; j += 256) {
        float x = x2[3 * j], y = x2[3 * j + 1], z = x2[3 * j + 2];
        pts[j] = make_float4(x, y, z, x * x + y * y + z * z);
    }
    __syncthreads();

    // ---- phase 1: knn ----
    {
        const int lq = threadIdx.x >> 2;
        const int q = qb + lq;
        const int sub = threadIdx.x & 3;
        const float qx = xyz1[3 * q], qy = xyz1[3 * q + 1], qz = xyz1[3 * q + 2];
        const float ax = -2.0f * qx, ay = -2.0f * qy, az = -2.0f * qz;

        float b0 = 3.4e38f, b1 = 3.4e38f, b2 = 3.4e38f;
        int i0 = 0, i1 = 0, i2 = 0;
#pragma unroll 8
        for (int i = 0; i < 256; i++) {
            const int j = sub + 4 * i;
            float4 p = pts[j];
            float v = fmaf(ax, p.x, fmaf(ay, p.y, fmaf(az, p.z, p.w)));
            if (v < b2) {
                if (v < b1) {
                    if (v < b0) { b2 = b1; i2 = i1; b1 = b0; i1 = i0; b0 = v; i0 = j; }
                    else        { b2 = b1; i2 = i1; b1 = v; i1 = j; }
                } else { b2 = v; i2 = j; }
            }
        }
#pragma unroll
        for (int dlt = 1; dlt <= 2; dlt <<= 1) {
            float c0 = __shfl_xor_sync(0xffffffffu, b0, dlt);
            float c1 = __shfl_xor_sync(0xffffffffu, b1, dlt);
            float c2 = __shfl_xor_sync(0xffffffffu, b2, dlt);
            int k0 = __shfl_xor_sync(0xffffffffu, i0, dlt);
            int k1 = __shfl_xor_sync(0xffffffffu, i1, dlt);
            int k2 = __shfl_xor_sync(0xffffffffu, i2, dlt);
            if (c0 < b0) {   // full triple swap keeps b-triple sorted
                float tf; int ti;
                tf = b0; b0 = c0; c0 = tf; ti = i0; i0 = k0; k0 = ti;
                tf = b1; b1 = c1; c1 = tf; ti = i1; i1 = k1; k1 = ti;
                tf = b2; b2 = c2; c2 = tf; ti = i2; i2 = k2; k2 = ti;
            }
            if (c0 < b1) {
                if (b1 < c1) { b2 = b1; i2 = i1; } else { b2 = c1; i2 = k1; }
                b1 = c0; i1 = k0;
            } else if (c0 < b2) { b2 = c0; i2 = k0; }
            (void)c2; (void)k2;
        }
        if (sub == 0) {
            float4 p0 = pts[i0], p1 = pts[i1], p2 = pts[i2];
            float dx, dy, dz;
            dx = qx - p0.x; dy = qy - p0.y; dz = qz - p0.z;
            float d0 = fmaxf(dx * dx + dy * dy + dz * dz, 1e-10f);
            dx = qx - p1.x; dy = qy - p1.y; dz = qz - p1.z;
            float d1 = fmaxf(dx * dx + dy * dy + dz * dz, 1e-10f);
            dx = qx - p2.x; dy = qy - p2.y; dz = qz - p2.z;
            float d2 = fmaxf(dx * dx + dy * dy + dz * dz, 1e-10f);
            float w0 = 1.0f / d0, w1 = 1.0f / d1, w2 = 1.0f / d2;
            float inv = 1.0f / (w0 + w1 + w2);
            sidx[lq * 3] = i0; sidx[lq * 3 + 1] = i1; sidx[lq * 3 + 2] = i2;
            swt[lq * 3] = w0 * inv; swt[lq * 3 + 1] = w1 * inv; swt[lq * 3 + 2] = w2 * inv;
        }
    }
    __syncthreads();

    // ---- phase 2: fp16 gather + concat (warp per query, 8 iterations) ----
    const int wq = threadIdx.x >> 5;
    const int lane = threadIdx.x & 31;
    const __half* f2 = g_feat2h + (size_t)b * N2 * C2;
#pragma unroll
    for (int it = 0; it < 8; it++) {
        const int lq = it * 8 + wq;
        const int q = qb + lq;
        const int i0 = sidx[lq * 3], i1 = sidx[lq * 3 + 1], i2 = sidx[lq * 3 + 2];
        const float w0 = swt[lq * 3], w1 = swt[lq * 3 + 1], w2 = swt[lq * 3 + 2];

        const uint4 v0 = ((const uint4*)(f2 + (size_t)i0 * C2))[lane];
        const uint4 v1 = ((const uint4*)(f2 + (size_t)i1 * C2))[lane];
        const uint4 v2 = ((const uint4*)(f2 + (size_t)i2 * C2))[lane];
        const __half2* h0 = (const __half2*)&v0;
        const __half2* h1 = (const __half2*)&v1;
        const __half2* h2 = (const __half2*)&v2;
        uint4 ov;
        __half2* oh = (__half2*)&ov;
#pragma unroll
        for (int k = 0; k < 4; k++) {
            float2 a = __half22float2(h0[k]);
            float2 d = __half22float2(h1[k]);
            float2 e = __half22float2(h2[k]);
            oh[k] = __floats2half2_rn(w0 * a.x + w1 * d.x + w2 * e.x,
                                      w0 * a.y + w1 * d.y + w2 * e.y);
        }
        __half* x = g_X + (size_t)q * DIN;
        ((uint4*)x)[lane] = ov;

        float4 f = ((const float4*)(feat1 + (size_t)q * C1))[lane];
        __half2 f0 = __floats2half2_rn(f.x, f.y);
        __half2 f1h = __floats2half2_rn(f.z, f.w);
        *(__half2*)(x + C2 + lane * 4) = f0;
        *(__half2*)(x + C2 + lane * 4 + 2) = f1h;
    }
}

// ---------------------------------------------------------------------------
// Kernel B: feat2 -> fp16 (8 elems/thread: 2x LDG.128 -> 1x STG.128)
//           AND W1/W2 transpose+fp16, one launch.
// ---------------------------------------------------------------------------
#define F2H_BLOCKS 2048   // 16*1024*256 / (256*8)
#define PREPW_BLOCKS 640

__global__ void prep_all(const float* __restrict__ feat2,
                         const float* __restrict__ W1,
                         const float* __restrict__ W2) {
    if (blockIdx.x < F2H_BLOCKS) {
        const size_t i = ((size_t)blockIdx.x * 256 + threadIdx.x) * 8;
        float4 v0 = *(const float4*)(feat2 + i);
        float4 v1 = *(const float4*)(feat2 + i + 4);
        __half2 h0 = __floats2half2_rn(v0.x, v0.y);
        __half2 h1 = __floats2half2_rn(v0.z, v0.w);
        __half2 h2 = __floats2half2_rn(v1.x, v1.y);
        __half2 h3 = __floats2half2_rn(v1.z, v1.w);
        uint4 o;
        o.x = *(const uint32_t*)&h0;
        o.y = *(const uint32_t*)&h1;
        o.z = *(const uint32_t*)&h2;
        o.w = *(const uint32_t*)&h3;
        *(uint4*)(g_feat2h + i) = o;
    } else {
        int i = (blockIdx.x - F2H_BLOCKS) * 256 + threadIdx.x;
        if (i < DIN * DOUT) {
            int k = i / DOUT, n = i % DOUT;
            g_W1T[n * DIN + k] = __float2half(W1[i]);
        } else {
            int j = i - DIN * DOUT;
            int k = j / DOUT, n = j % DOUT;
            g_W2T[n * DOUT + k] = __float2half(W2[j]);
        }
    }
}

// ---------------------------------------------------------------------------
// HGEMM (R8, proven): CTA tile 128x128, BK=64, 256 threads, 64x32 warp tiles,
// 3-stage cp.async pipeline, one __syncthreads per chunk, f32 accumulate.
// ---------------------------------------------------------------------------
#define HGEMM_SMEM (3 * 32768)

template<int K, bool WRITE_H>
__global__ __launch_bounds__(256, 2) void hgemm(
    const __half* __restrict__ A, const __half* __restrict__ Bt,
    const float* __restrict__ bias,
    __half* __restrict__ outH, float* __restrict__ outF) {
    constexpr int NC = K / 64;
    extern __shared__ char smem[];
    const uint32_t sb = smem_u32(smem);
    const int tid = threadIdx.x;
    const int w = tid >> 5, lane = tid & 31;
    const int wy = w >> 2, wx = w & 3;
    const int mblk = blockIdx.y * 128, nblk = blockIdx.x * 128;

    const char* Abase = (const char*)(A + (size_t)mblk * K);
    const char* Bbase = (const char*)(Bt + (size_t)nblk * K);
    const int row_l = tid >> 3;
    const int ch_l = tid & 7;

    float acc[4][4][4];
#pragma unroll
    for (int i = 0; i < 4; i++)
#pragma unroll
        for (int j = 0; j < 4; j++)
#pragma unroll
            for (int k = 0; k < 4; k++) acc[i][j][k] = 0.0f;

    auto issue = [&](int c) {
        const uint32_t base = sb + (uint32_t)(c % 3) * 32768u;
        const char* ag = Abase + (size_t)c * 128;
        const char* bg = Bbase + (size_t)c * 128;
#pragma unroll
        for (int rr = 0; rr < 4; rr++) {
            const int row = row_l + rr * 32;
            const uint32_t off = (uint32_t)(row * 128 + ch_l * 16);
            const uint32_t d = base + SWZ(off);
            CP_ASYNC16(d, ag + (size_t)row * (K * 2) + ch_l * 16);
            CP_ASYNC16(d + 16384, bg + (size_t)row * (K * 2) + ch_l * 16);
        }
        CP_COMMIT();
    };

    issue(0);
    issue(1);
#pragma unroll
    for (int c = 0; c < NC; c++) {
        if (c + 1 < NC) { CP_WAIT(1); } else { CP_WAIT(0); }
        __syncthreads();
        const uint32_t abase = sb + (uint32_t)(c % 3) * 32768u;
        const uint32_t bbase = abase + 16384u;
#pragma unroll
        for (int ks = 0; ks < 4; ks++) {
            uint32_t af[4][4];
#pragma unroll
            for (int mt = 0; mt < 4; mt++) {
                const int row = wy * 64 + mt * 16 + ((lane >> 3) & 1) * 8 + (lane & 7);
                const int ch = ks * 2 + (lane >> 4);
                ldmatrix_x4(af[mt], abase + SWZ((uint32_t)(row * 128 + ch * 16)));
            }
            uint32_t bf[4][2];
#pragma unroll
            for (int p = 0; p < 2; p++) {
                const int t = lane >> 3;
                const int nrow = wx * 32 + (2 * p + (t >> 1)) * 8 + (lane & 7);
                const int ch = ks * 2 + (t & 1);
                uint32_t r[4];
                ldmatrix_x4(r, bbase + SWZ((uint32_t)(nrow * 128 + ch * 16)));
                bf[2 * p][0] = r[0]; bf[2 * p][1] = r[1];
                bf[2 * p + 1][0] = r[2]; bf[2 * p + 1][1] = r[3];
            }
#pragma unroll
            for (int mt = 0; mt < 4; mt++)
#pragma unroll
                for (int nt = 0; nt < 4; nt++)
                    mma16816(acc[mt][nt], af[mt], bf[nt]);
        }
        if (c + 2 < NC) issue(c + 2);
    }

#pragma unroll
    for (int mt = 0; mt < 4; mt++) {
#pragma unroll
        for (int nt = 0; nt < 4; nt++) {
            const int row0 = mblk + wy * 64 + mt * 16 + (lane >> 2);
            const int col = nblk + wx * 32 + nt * 8 + 2 * (lane & 3);
            const float bz0 = bias[col], bz1 = bias[col + 1];
            float v00 = fmaxf(acc[mt][nt][0] + bz0, 0.0f);
            float v01 = fmaxf(acc[mt][nt][1] + bz1, 0.0f);
            float v10 = fmaxf(acc[mt][nt][2] + bz0, 0.0f);
            float v11 = fmaxf(acc[mt][nt][3] + bz1, 0.0f);
            if constexpr (WRITE_H) {
                *(__half2*)(outH + (size_t)row0 * 256 + col) = __floats2half2_rn(v00, v01);
                *(__half2*)(outH + (size_t)(row0 + 8) * 256 + col) = __floats2half2_rn(v10, v11);
            } else {
                float2 o0; o0.x = v00; o0.y = v01;
                float2 o1; o1.x = v10; o1.y = v11;
                *(float2*)(outF + (size_t)row0 * 256 + col) = o0;
                *(float2*)(outF + (size_t)(row0 + 8) * 256 + col) = o1;
            }
        }
    }
}

// ---------------------------------------------------------------------------
extern "C" void kernel_launch(void* const* d_in, const int* in_sizes, int n_in,
                              void* d_out, int out_size) {
    const float* xyz1  = (const float*)d_in[0];
    const float* feat1 = (const float*)d_in[1];
    const float* xyz2  = (const float*)d_in[2];
    const float* feat2 = (const float*)d_in[3];
    const float* W1    = (const float*)d_in[4];
    const float* b1    = (const float*)d_in[5];
    const float* W2    = (const float*)d_in[6];
    const float* b2    = (const float*)d_in[7];
    float* out = (float*)d_out;

    __half *X, *H, *W1T, *W2T;
    cudaGetSymbolAddress((void**)&X, g_X);
    cudaGetSymbolAddress((void**)&H, g_H);
    cudaGetSymbolAddress((void**)&W1T, g_W1T);
    cudaGetSymbolAddress((void**)&W2T, g_W2T);

    cudaFuncSetAttribute((const void*)hgemm<DIN, true>,
                         cudaFuncAttributeMaxDynamicSharedMemorySize, HGEMM_SMEM);
    cudaFuncSetAttribute((const void*)hgemm<DOUT, false>,
                         cudaFuncAttributeMaxDynamicSharedMemorySize, HGEMM_SMEM);

    prep_all<<<F2H_BLOCKS + PREPW_BLOCKS, 256>>>(feat2, W1, W2);
    knn_interp_kernel<<<NQ / 64, 256>>>(xyz1, xyz2, feat1);

    dim3 grid(DOUT / 128, NQ / 128);
    hgemm<DIN, true><<<grid, 256, HGEMM_SMEM>>>(X, W1T, b1, H, nullptr);
    hgemm<DOUT, false><<<grid, 256, HGEMM_SMEM>>>(H, W2T, b2, nullptr, out);
}

// round 15
// speedup vs baseline: 1.9628x; 1.0156x over previous
#include <cuda_runtime.h>
#include <cuda_fp16.h>
#include <cuda_bf16.h>
#include <cstdint>

#define BB 16
#define N1 4096
#define N2 1024
#define C1 128
#define C2 256
#define DIN 384
#define DOUT 256
#define NQ (BB * N1)

// ---------------- device scratch ----------------
__device__ __align__(16) __half g_X[(size_t)NQ * DIN];
__device__ __align__(16) __half g_H[(size_t)NQ * DOUT];
__device__ __align__(16) __half g_W1T[DOUT * DIN];
__device__ __align__(16) __half g_W2T[DOUT * DOUT];
__device__ __align__(16) __half g_feat2h[(size_t)BB * N2 * C2];

// ---------------- PTX helpers (portable, OK on compute_103) ----------------
__device__ __forceinline__ uint32_t smem_u32(const void* p) {
    uint32_t a;
    asm("{ .reg .u64 t; cvta.to.shared.u64 t, %1; cvt.u32.u64 %0, t; }" : "=r"(a) : "l"(p));
    return a;
}
#define CP_ASYNC16(dst, src) \
    asm volatile("cp.async.cg.shared.global [%0], [%1], 16;" :: "r"(dst), "l"(src))
#define CP_COMMIT() asm volatile("cp.async.commit_group;" ::: "memory")
#define CP_WAIT(n)  asm volatile("cp.async.wait_group %0;" :: "n"(n) : "memory")

__device__ __forceinline__ void ldmatrix_x4(uint32_t* r, uint32_t addr) {
    asm volatile("ldmatrix.sync.aligned.m8n8.x4.shared.b16 {%0,%1,%2,%3}, [%4];"
                 : "=r"(r[0]), "=r"(r[1]), "=r"(r[2]), "=r"(r[3]) : "r"(addr));
}
__device__ __forceinline__ void mma16816(float* d, const uint32_t* a, const uint32_t* b) {
    asm volatile(
        "mma.sync.aligned.m16n8k16.row.col.f32.f16.f16.f32 "
        "{%0,%1,%2,%3}, {%4,%5,%6,%7}, {%8,%9}, {%0,%1,%2,%3};"
        : "+f"(d[0]), "+f"(d[1]), "+f"(d[2]), "+f"(d[3])
        : "r"(a[0]), "r"(a[1]), "r"(a[2]), "r"(a[3]), "r"(b[0]), "r"(b[1]));
}
#define SWZ(bo) ((bo) ^ (((bo) >> 3) & 0x70))

// ---------------------------------------------------------------------------
// Kernel A (R8, proven): fused 3-NN + interpolation + concat. 64 queries/blk.
// ---------------------------------------------------------------------------
__global__ __launch_bounds__(256) void knn_interp_kernel(
    const float* __restrict__ xyz1, const float* __restrict__ xyz2,
    const float* __restrict__ feat1) {
    __shared__ float4 pts[N2];
    __shared__ int   sidx[64 * 3];
    __shared__ float swt[64 * 3];

    const int qb = blockIdx.x * 64;
    const int b = qb >> 12;
    const float* x2 = xyz2 + (size_t)b * N2 * 3;
    for (int j = threadIdx.x; j < N2; j += 256) {
        float x = x2[3 * j], y = x2[3 * j + 1], z = x2[3 * j + 2];
        pts[j] = make_float4(x, y, z, x * x + y * y + z * z);
    }
    __syncthreads();

    // ---- phase 1: knn ----
    {
        const int lq = threadIdx.x >> 2;
        const int q = qb + lq;
        const int sub = threadIdx.x & 3;
        const float qx = xyz1[3 * q], qy = xyz1[3 * q + 1], qz = xyz1[3 * q + 2];
        const float ax = -2.0f * qx, ay = -2.0f * qy, az = -2.0f * qz;

        float b0 = 3.4e38f, b1 = 3.4e38f, b2 = 3.4e38f;
        int i0 = 0, i1 = 0, i2 = 0;
#pragma unroll 8
        for (int i = 0; i < 256; i++) {
            const int j = sub + 4 * i;
            float4 p = pts[j];
            float v = fmaf(ax, p.x, fmaf(ay, p.y, fmaf(az, p.z, p.w)));
            if (v < b2) {
                if (v < b1) {
                    if (v < b0) { b2 = b1; i2 = i1; b1 = b0; i1 = i0; b0 = v; i0 = j; }
                    else        { b2 = b1; i2 = i1; b1 = v; i1 = j; }
                } else { b2 = v; i2 = j; }
            }
        }
#pragma unroll
        for (int dlt = 1; dlt <= 2; dlt <<= 1) {
            float c0 = __shfl_xor_sync(0xffffffffu, b0, dlt);
            float c1 = __shfl_xor_sync(0xffffffffu, b1, dlt);
            float c2 = __shfl_xor_sync(0xffffffffu, b2, dlt);
            int k0 = __shfl_xor_sync(0xffffffffu, i0, dlt);
            int k1 = __shfl_xor_sync(0xffffffffu, i1, dlt);
            int k2 = __shfl_xor_sync(0xffffffffu, i2, dlt);
            if (c0 < b0) {   // full triple swap keeps b-triple sorted
                float tf; int ti;
                tf = b0; b0 = c0; c0 = tf; ti = i0; i0 = k0; k0 = ti;
                tf = b1; b1 = c1; c1 = tf; ti = i1; i1 = k1; k1 = ti;
                tf = b2; b2 = c2; c2 = tf; ti = i2; i2 = k2; k2 = ti;
            }
            if (c0 < b1) {
                if (b1 < c1) { b2 = b1; i2 = i1; } else { b2 = c1; i2 = k1; }
                b1 = c0; i1 = k0;
            } else if (c0 < b2) { b2 = c0; i2 = k0; }
            (void)c2; (void)k2;
        }
        if (sub == 0) {
            float4 p0 = pts[i0], p1 = pts[i1], p2 = pts[i2];
            float dx, dy, dz;
            dx = qx - p0.x; dy = qy - p0.y; dz = qz - p0.z;
            float d0 = fmaxf(dx * dx + dy * dy + dz * dz, 1e-10f);
            dx = qx - p1.x; dy = qy - p1.y; dz = qz - p1.z;
            float d1 = fmaxf(dx * dx + dy * dy + dz * dz, 1e-10f);
            dx = qx - p2.x; dy = qy - p2.y; dz = qz - p2.z;
            float d2 = fmaxf(dx * dx + dy * dy + dz * dz, 1e-10f);
            float w0 = 1.0f / d0, w1 = 1.0f / d1, w2 = 1.0f / d2;
            float inv = 1.0f / (w0 + w1 + w2);
            sidx[lq * 3] = i0; sidx[lq * 3 + 1] = i1; sidx[lq * 3 + 2] = i2;
            swt[lq * 3] = w0 * inv; swt[lq * 3 + 1] = w1 * inv; swt[lq * 3 + 2] = w2 * inv;
        }
    }
    __syncthreads();

    // ---- phase 2: fp16 gather + concat (warp per query, 8 iterations) ----
    const int wq = threadIdx.x >> 5;
    const int lane = threadIdx.x & 31;
    const __half* f2 = g_feat2h + (size_t)b * N2 * C2;
#pragma unroll
    for (int it = 0; it < 8; it++) {
        const int lq = it * 8 + wq;
        const int q = qb + lq;
        const int i0 = sidx[lq * 3], i1 = sidx[lq * 3 + 1], i2 = sidx[lq * 3 + 2];
        const float w0 = swt[lq * 3], w1 = swt[lq * 3 + 1], w2 = swt[lq * 3 + 2];

        const uint4 v0 = ((const uint4*)(f2 + (size_t)i0 * C2))[lane];
        const uint4 v1 = ((const uint4*)(f2 + (size_t)i1 * C2))[lane];
        const uint4 v2 = ((const uint4*)(f2 + (size_t)i2 * C2))[lane];
        const __half2* h0 = (const __half2*)&v0;
        const __half2* h1 = (const __half2*)&v1;
        const __half2* h2 = (const __half2*)&v2;
        uint4 ov;
        __half2* oh = (__half2*)&ov;
#pragma unroll
        for (int k = 0; k < 4; k++) {
            float2 a = __half22float2(h0[k]);
            float2 d = __half22float2(h1[k]);
            float2 e = __half22float2(h2[k]);
            oh[k] = __floats2half2_rn(w0 * a.x + w1 * d.x + w2 * e.x,
                                      w0 * a.y + w1 * d.y + w2 * e.y);
        }
        __half* x = g_X + (size_t)q * DIN;
        ((uint4*)x)[lane] = ov;

        float4 f = ((const float4*)(feat1 + (size_t)q * C1))[lane];
        __half2 f0 = __floats2half2_rn(f.x, f.y);
        __half2 f1h = __floats2half2_rn(f.z, f.w);
        *(__half2*)(x + C2 + lane * 4) = f0;
        *(__half2*)(x + C2 + lane * 4 + 2) = f1h;
    }
}

// ---------------------------------------------------------------------------
// Kernel B (R14): feat2 -> fp16 (8 elems/thread) AND W prep, one launch.
// ---------------------------------------------------------------------------
#define F2H_BLOCKS 2048
#define PREPW_BLOCKS 640

__global__ void prep_all(const float* __restrict__ feat2,
                         const float* __restrict__ W1,
                         const float* __restrict__ W2) {
    if (blockIdx.x < F2H_BLOCKS) {
        const size_t i = ((size_t)blockIdx.x * 256 + threadIdx.x) * 8;
        float4 v0 = *(const float4*)(feat2 + i);
        float4 v1 = *(const float4*)(feat2 + i + 4);
        __half2 h0 = __floats2half2_rn(v0.x, v0.y);
        __half2 h1 = __floats2half2_rn(v0.z, v0.w);
        __half2 h2 = __floats2half2_rn(v1.x, v1.y);
        __half2 h3 = __floats2half2_rn(v1.z, v1.w);
        uint4 o;
        o.x = *(const uint32_t*)&h0;
        o.y = *(const uint32_t*)&h1;
        o.z = *(const uint32_t*)&h2;
        o.w = *(const uint32_t*)&h3;
        *(uint4*)(g_feat2h + i) = o;
    } else {
        int i = (blockIdx.x - F2H_BLOCKS) * 256 + threadIdx.x;
        if (i < DIN * DOUT) {
            int k = i / DOUT, n = i % DOUT;
            g_W1T[n * DIN + k] = __float2half(W1[i]);
        } else {
            int j = i - DIN * DOUT;
            int k = j / DOUT, n = j % DOUT;
            g_W2T[n * DOUT + k] = __float2half(W2[j]);
        }
    }
}

// ---------------------------------------------------------------------------
// HGEMM1 (R8, proven): CTA 128x128, BK=64, 3-stage cp.async, one sync/chunk.
// ---------------------------------------------------------------------------
#define HGEMM_SMEM (3 * 32768)

__global__ __launch_bounds__(256, 2) void hgemm1(
    const __half* __restrict__ A, const __half* __restrict__ Bt,
    const float* __restrict__ bias, __half* __restrict__ outH) {
    constexpr int K = DIN;
    constexpr int NC = K / 64;
    extern __shared__ char smem[];
    const uint32_t sb = smem_u32(smem);
    const int tid = threadIdx.x;
    const int w = tid >> 5, lane = tid & 31;
    const int wy = w >> 2, wx = w & 3;
    const int mblk = blockIdx.y * 128, nblk = blockIdx.x * 128;

    const char* Abase = (const char*)(A + (size_t)mblk * K);
    const char* Bbase = (const char*)(Bt + (size_t)nblk * K);
    const int row_l = tid >> 3;
    const int ch_l = tid & 7;

    float acc[4][4][4];
#pragma unroll
    for (int i = 0; i < 4; i++)
#pragma unroll
        for (int j = 0; j < 4; j++)
#pragma unroll
            for (int k = 0; k < 4; k++) acc[i][j][k] = 0.0f;

    auto issue = [&](int c) {
        const uint32_t base = sb + (uint32_t)(c % 3) * 32768u;
        const char* ag = Abase + (size_t)c * 128;
        const char* bg = Bbase + (size_t)c * 128;
#pragma unroll
        for (int rr = 0; rr < 4; rr++) {
            const int row = row_l + rr * 32;
            const uint32_t off = (uint32_t)(row * 128 + ch_l * 16);
            const uint32_t d = base + SWZ(off);
            CP_ASYNC16(d, ag + (size_t)row * (K * 2) + ch_l * 16);
            CP_ASYNC16(d + 16384, bg + (size_t)row * (K * 2) + ch_l * 16);
        }
        CP_COMMIT();
    };

    issue(0);
    issue(1);
#pragma unroll
    for (int c = 0; c < NC; c++) {
        if (c + 1 < NC) { CP_WAIT(1); } else { CP_WAIT(0); }
        __syncthreads();
        const uint32_t abase = sb + (uint32_t)(c % 3) * 32768u;
        const uint32_t bbase = abase + 16384u;
#pragma unroll
        for (int ks = 0; ks < 4; ks++) {
            uint32_t af[4][4];
#pragma unroll
            for (int mt = 0; mt < 4; mt++) {
                const int row = wy * 64 + mt * 16 + ((lane >> 3) & 1) * 8 + (lane & 7);
                const int ch = ks * 2 + (lane >> 4);
                ldmatrix_x4(af[mt], abase + SWZ((uint32_t)(row * 128 + ch * 16)));
            }
            uint32_t bf[4][2];
#pragma unroll
            for (int p = 0; p < 2; p++) {
                const int t = lane >> 3;
                const int nrow = wx * 32 + (2 * p + (t >> 1)) * 8 + (lane & 7);
                const int ch = ks * 2 + (t & 1);
                uint32_t r[4];
                ldmatrix_x4(r, bbase + SWZ((uint32_t)(nrow * 128 + ch * 16)));
                bf[2 * p][0] = r[0]; bf[2 * p][1] = r[1];
                bf[2 * p + 1][0] = r[2]; bf[2 * p + 1][1] = r[3];
            }
#pragma unroll
            for (int mt = 0; mt < 4; mt++)
#pragma unroll
                for (int nt = 0; nt < 4; nt++)
                    mma16816(acc[mt][nt], af[mt], bf[nt]);
        }
        if (c + 2 < NC) issue(c + 2);
    }

#pragma unroll
    for (int mt = 0; mt < 4; mt++) {
#pragma unroll
        for (int nt = 0; nt < 4; nt++) {
            const int row0 = mblk + wy * 64 + mt * 16 + (lane >> 2);
            const int col = nblk + wx * 32 + nt * 8 + 2 * (lane & 3);
            const float bz0 = bias[col], bz1 = bias[col + 1];
            float v00 = fmaxf(acc[mt][nt][0] + bz0, 0.0f);
            float v01 = fmaxf(acc[mt][nt][1] + bz1, 0.0f);
            float v10 = fmaxf(acc[mt][nt][2] + bz0, 0.0f);
            float v11 = fmaxf(acc[mt][nt][3] + bz1, 0.0f);
            *(__half2*)(outH + (size_t)row0 * 256 + col) = __floats2half2_rn(v00, v01);
            *(__half2*)(outH + (size_t)(row0 + 8) * 256 + col) = __floats2half2_rn(v10, v11);
        }
    }
}

// ---------------------------------------------------------------------------
// HGEMM2 persistent: 296 CTAs (2/SM, one wave). Each CTA pins nblk = blk&1,
// loads the FULL 64KB B tile (W2T nblk-block, 4 K-chunks) into smem ONCE,
// then streams A chunks (16KB, 3-stage ring) across ~3.5 M-tiles.
// Inner 4-ks compute identical to R8 (same accumulation order).
// smem = 64KB B + 48KB A = 112KB -> 2 CTAs/SM.
// ---------------------------------------------------------------------------
#define G2_SMEM (65536 + 3 * 16384)
#define G2_GRID 296

__global__ __launch_bounds__(256, 2) void hgemm2_persist(
    const __half* __restrict__ A, const __half* __restrict__ Bt,
    const float* __restrict__ bias, float* __restrict__ outF) {
    extern __shared__ char smem[];
    const uint32_t sb = smem_u32(smem);
    const int tid = threadIdx.x;
    const int w = tid >> 5, lane = tid & 31;
    const int wy = w >> 2, wx = w & 3;
    const int nb = blockIdx.x & 1;
    const int nblk = nb * 128;
    const int mbase = blockIdx.x >> 1;                  // 0..147
    const int ntiles = (512 - mbase + 147) / 148;       // 3 or 4
    const int total = ntiles * 4;

    const int row_l = tid >> 3;
    const int ch_l = tid & 7;

    float acc[4][4][4];
#pragma unroll
    for (int i = 0; i < 4; i++)
#pragma unroll
        for (int j = 0; j < 4; j++)
#pragma unroll
            for (int k = 0; k < 4; k++) acc[i][j][k] = 0.0f;

    // hoist bias (same columns for every tile)
    float bz[4][2];
#pragma unroll
    for (int nt = 0; nt < 4; nt++) {
        const int col = nblk + wx * 32 + nt * 8 + 2 * (lane & 3);
        bz[nt][0] = bias[col];
        bz[nt][1] = bias[col + 1];
    }

    // resident B: 4 chunks x (128 rows x 128B, SW128) at chunk*16384
    {
        const char* bg = (const char*)Bt;
#pragma unroll
        for (int r = 0; r < 16; r++) {
            const int idx = tid + r * 256;      // 0..4095 uint4
            const int ck = idx >> 10;
            const int row = (idx >> 3) & 127;
            const int s = idx & 7;
            const uint32_t d = sb + (uint32_t)(ck * 16384)
                             + SWZ((uint32_t)(row * 128 + s * 16));
            CP_ASYNC16(d, bg + (size_t)(nblk + row) * 512 + ck * 128 + s * 16);
        }
    }

    auto issueA = [&](int ct) {
        const int tile = ct >> 2, c = ct & 3;
        const size_t mrow = (size_t)(mbase + tile * 148) * 128;
        const char* ag = (const char*)(A + mrow * 256) + c * 128;
        const uint32_t base = sb + 65536u + (uint32_t)(ct % 3) * 16384u;
#pragma unroll
        for (int rr = 0; rr < 4; rr++) {
            const int row = row_l + rr * 32;
            const uint32_t d = base + SWZ((uint32_t)(row * 128 + ch_l * 16));
            CP_ASYNC16(d, ag + (size_t)row * 512 + ch_l * 16);
        }
    };

    issueA(0); CP_COMMIT();      // group 0: B + A0
    issueA(1); CP_COMMIT();      // group 1: A1

    for (int ct = 0; ct < total; ct++) {
        if (ct + 1 < total) { CP_WAIT(1); } else { CP_WAIT(0); }
        __syncthreads();
        const uint32_t abase = sb + 65536u + (uint32_t)(ct % 3) * 16384u;
        const uint32_t bbase = sb + (uint32_t)((ct & 3) * 16384);
#pragma unroll
        for (int ks = 0; ks < 4; ks++) {
            uint32_t af[4][4];
#pragma unroll
            for (int mt = 0; mt < 4; mt++) {
                const int row = wy * 64 + mt * 16 + ((lane >> 3) & 1) * 8 + (lane & 7);
                const int ch = ks * 2 + (lane >> 4);
                ldmatrix_x4(af[mt], abase + SWZ((uint32_t)(row * 128 + ch * 16)));
            }
            uint32_t bf[4][2];
#pragma unroll
            for (int p = 0; p < 2; p++) {
                const int t = lane >> 3;
                const int nrow = wx * 32 + (2 * p + (t >> 1)) * 8 + (lane & 7);
                const int ch = ks * 2 + (t & 1);
                uint32_t r[4];
                ldmatrix_x4(r, bbase + SWZ((uint32_t)(nrow * 128 + ch * 16)));
                bf[2 * p][0] = r[0]; bf[2 * p][1] = r[1];
                bf[2 * p + 1][0] = r[2]; bf[2 * p + 1][1] = r[3];
            }
#pragma unroll
            for (int mt = 0; mt < 4; mt++)
#pragma unroll
                for (int nt = 0; nt < 4; nt++)
                    mma16816(acc[mt][nt], af[mt], bf[nt]);
        }
        if (ct + 2 < total) { issueA(ct + 2); CP_COMMIT(); }

        if ((ct & 3) == 3) {
            // epilogue for finished tile, then reset accumulators
            const int mblk = (mbase + (ct >> 2) * 148) * 128;
#pragma unroll
            for (int mt = 0; mt < 4; mt++) {
#pragma unroll
                for (int nt = 0; nt < 4; nt++) {
                    const int row0 = mblk + wy * 64 + mt * 16 + (lane >> 2);
                    const int col = nblk + wx * 32 + nt * 8 + 2 * (lane & 3);
                    float2 o0, o1;
                    o0.x = fmaxf(acc[mt][nt][0] + bz[nt][0], 0.0f);
                    o0.y = fmaxf(acc[mt][nt][1] + bz[nt][1], 0.0f);
                    o1.x = fmaxf(acc[mt][nt][2] + bz[nt][0], 0.0f);
                    o1.y = fmaxf(acc[mt][nt][3] + bz[nt][1], 0.0f);
                    *(float2*)(outF + (size_t)row0 * 256 + col) = o0;
                    *(float2*)(outF + (size_t)(row0 + 8) * 256 + col) = o1;
                    acc[mt][nt][0] = 0.0f; acc[mt][nt][1] = 0.0f;
                    acc[mt][nt][2] = 0.0f; acc[mt][nt][3] = 0.0f;
                }
            }
        }
    }
}

// ---------------------------------------------------------------------------
extern "C" void kernel_launch(void* const* d_in, const int* in_sizes, int n_in,
                              void* d_out, int out_size) {
    const float* xyz1  = (const float*)d_in[0];
    const float* feat1 = (const float*)d_in[1];
    const float* xyz2  = (const float*)d_in[2];
    const float* feat2 = (const float*)d_in[3];
    const float* W1    = (const float*)d_in[4];
    const float* b1    = (const float*)d_in[5];
    const float* W2    = (const float*)d_in[6];
    const float* b2    = (const float*)d_in[7];
    float* out = (float*)d_out;

    __half *X, *H, *W1T, *W2T;
    cudaGetSymbolAddress((void**)&X, g_X);
    cudaGetSymbolAddress((void**)&H, g_H);
    cudaGetSymbolAddress((void**)&W1T, g_W1T);
    cudaGetSymbolAddress((void**)&W2T, g_W2T);

    cudaFuncSetAttribute((const void*)hgemm1,
                         cudaFuncAttributeMaxDynamicSharedMemorySize, HGEMM_SMEM);
    cudaFuncSetAttribute((const void*)hgemm2_persist,
                         cudaFuncAttributeMaxDynamicSharedMemorySize, G2_SMEM);

    prep_all<<<F2H_BLOCKS + PREPW_BLOCKS, 256>>>(feat2, W1, W2);
    knn_interp_kernel<<<NQ / 64, 256>>>(xyz1, xyz2, feat1);

    dim3 grid(DOUT / 128, NQ / 128);
    hgemm1<<<grid, 256, HGEMM_SMEM>>>(X, W1T, b1, H);
    hgemm2_persist<<<G2_GRID, 256, G2_SMEM>>>(H, W2T, b2, out);
}

// round 16
// speedup vs baseline: 1.9711x; 1.0043x over previous
#include <cuda_runtime.h>
#include <cuda_fp16.h>
#include <cuda_bf16.h>
#include <cstdint>

#define BB 16
#define N1 4096
#define N2 1024
#define C1 128
#define C2 256
#define DIN 384
#define DOUT 256
#define NQ (BB * N1)

// ---------------- device scratch ----------------
__device__ __align__(16) __half g_X[(size_t)NQ * DIN];
__device__ __align__(16) __half g_H[(size_t)NQ * DOUT];
__device__ __align__(16) __half g_W1T[DOUT * DIN];
__device__ __align__(16) __half g_W2T[DOUT * DOUT];
__device__ __align__(16) __half g_feat2h[(size_t)BB * N2 * C2];

// ---------------- PTX helpers (portable, OK on compute_103) ----------------
__device__ __forceinline__ uint32_t smem_u32(const void* p) {
    uint32_t a;
    asm("{ .reg .u64 t; cvta.to.shared.u64 t, %1; cvt.u32.u64 %0, t; }" : "=r"(a) : "l"(p));
    return a;
}
#define CP_ASYNC16(dst, src) \
    asm volatile("cp.async.cg.shared.global [%0], [%1], 16;" :: "r"(dst), "l"(src))
#define CP_COMMIT() asm volatile("cp.async.commit_group;" ::: "memory")
#define CP_WAIT(n)  asm volatile("cp.async.wait_group %0;" :: "n"(n) : "memory")

__device__ __forceinline__ void ldmatrix_x4(uint32_t* r, uint32_t addr) {
    asm volatile("ldmatrix.sync.aligned.m8n8.x4.shared.b16 {%0,%1,%2,%3}, [%4];"
                 : "=r"(r[0]), "=r"(r[1]), "=r"(r[2]), "=r"(r[3]) : "r"(addr));
}
__device__ __forceinline__ void mma16816(float* d, const uint32_t* a, const uint32_t* b) {
    asm volatile(
        "mma.sync.aligned.m16n8k16.row.col.f32.f16.f16.f32 "
        "{%0,%1,%2,%3}, {%4,%5,%6,%7}, {%8,%9}, {%0,%1,%2,%3};"
        : "+f"(d[0]), "+f"(d[1]), "+f"(d[2]), "+f"(d[3])
        : "r"(a[0]), "r"(a[1]), "r"(a[2]), "r"(a[3]), "r"(b[0]), "r"(b[1]));
}
#define SWZ(bo) ((bo) ^ (((bo) >> 3) & 0x70))

// ---------------------------------------------------------------------------
// Kernel A (R8, proven): fused 3-NN + interpolation + concat. 64 queries/blk.
// ---------------------------------------------------------------------------
__global__ __launch_bounds__(256) void knn_interp_kernel(
    const float* __restrict__ xyz1, const float* __restrict__ xyz2,
    const float* __restrict__ feat1) {
    __shared__ float4 pts[N2];
    __shared__ int   sidx[64 * 3];
    __shared__ float swt[64 * 3];

    const int qb = blockIdx.x * 64;
    const int b = qb >> 12;
    const float* x2 = xyz2 + (size_t)b * N2 * 3;
    for (int j = threadIdx.x; j < N2; j += 256) {
        float x = x2[3 * j], y = x2[3 * j + 1], z = x2[3 * j + 2];
        pts[j] = make_float4(x, y, z, x * x + y * y + z * z);
    }
    __syncthreads();

    // ---- phase 1: knn ----
    {
        const int lq = threadIdx.x >> 2;
        const int q = qb + lq;
        const int sub = threadIdx.x & 3;
        const float qx = xyz1[3 * q], qy = xyz1[3 * q + 1], qz = xyz1[3 * q + 2];
        const float ax = -2.0f * qx, ay = -2.0f * qy, az = -2.0f * qz;

        float b0 = 3.4e38f, b1 = 3.4e38f, b2 = 3.4e38f;
        int i0 = 0, i1 = 0, i2 = 0;
#pragma unroll 8
        for (int i = 0; i < 256; i++) {
            const int j = sub + 4 * i;
            float4 p = pts[j];
            float v = fmaf(ax, p.x, fmaf(ay, p.y, fmaf(az, p.z, p.w)));
            if (v < b2) {
                if (v < b1) {
                    if (v < b0) { b2 = b1; i2 = i1; b1 = b0; i1 = i0; b0 = v; i0 = j; }
                    else        { b2 = b1; i2 = i1; b1 = v; i1 = j; }
                } else { b2 = v; i2 = j; }
            }
        }
#pragma unroll
        for (int dlt = 1; dlt <= 2; dlt <<= 1) {
            float c0 = __shfl_xor_sync(0xffffffffu, b0, dlt);
            float c1 = __shfl_xor_sync(0xffffffffu, b1, dlt);
            float c2 = __shfl_xor_sync(0xffffffffu, b2, dlt);
            int k0 = __shfl_xor_sync(0xffffffffu, i0, dlt);
            int k1 = __shfl_xor_sync(0xffffffffu, i1, dlt);
            int k2 = __shfl_xor_sync(0xffffffffu, i2, dlt);
            if (c0 < b0) {   // full triple swap keeps b-triple sorted
                float tf; int ti;
                tf = b0; b0 = c0; c0 = tf; ti = i0; i0 = k0; k0 = ti;
                tf = b1; b1 = c1; c1 = tf; ti = i1; i1 = k1; k1 = ti;
                tf = b2; b2 = c2; c2 = tf; ti = i2; i2 = k2; k2 = ti;
            }
            if (c0 < b1) {
                if (b1 < c1) { b2 = b1; i2 = i1; } else { b2 = c1; i2 = k1; }
                b1 = c0; i1 = k0;
            } else if (c0 < b2) { b2 = c0; i2 = k0; }
            (void)c2; (void)k2;
        }
        if (sub == 0) {
            float4 p0 = pts[i0], p1 = pts[i1], p2 = pts[i2];
            float dx, dy, dz;
            dx = qx - p0.x; dy = qy - p0.y; dz = qz - p0.z;
            float d0 = fmaxf(dx * dx + dy * dy + dz * dz, 1e-10f);
            dx = qx - p1.x; dy = qy - p1.y; dz = qz - p1.z;
            float d1 = fmaxf(dx * dx + dy * dy + dz * dz, 1e-10f);
            dx = qx - p2.x; dy = qy - p2.y; dz = qz - p2.z;
            float d2 = fmaxf(dx * dx + dy * dy + dz * dz, 1e-10f);
            float w0 = 1.0f / d0, w1 = 1.0f / d1, w2 = 1.0f / d2;
            float inv = 1.0f / (w0 + w1 + w2);
            sidx[lq * 3] = i0; sidx[lq * 3 + 1] = i1; sidx[lq * 3 + 2] = i2;
            swt[lq * 3] = w0 * inv; swt[lq * 3 + 1] = w1 * inv; swt[lq * 3 + 2] = w2 * inv;
        }
    }
    __syncthreads();

    // ---- phase 2: fp16 gather + concat (warp per query, 8 iterations) ----
    const int wq = threadIdx.x >> 5;
    const int lane = threadIdx.x & 31;
    const __half* f2 = g_feat2h + (size_t)b * N2 * C2;
#pragma unroll
    for (int it = 0; it < 8; it++) {
        const int lq = it * 8 + wq;
        const int q = qb + lq;
        const int i0 = sidx[lq * 3], i1 = sidx[lq * 3 + 1], i2 = sidx[lq * 3 + 2];
        const float w0 = swt[lq * 3], w1 = swt[lq * 3 + 1], w2 = swt[lq * 3 + 2];

        const uint4 v0 = ((const uint4*)(f2 + (size_t)i0 * C2))[lane];
        const uint4 v1 = ((const uint4*)(f2 + (size_t)i1 * C2))[lane];
        const uint4 v2 = ((const uint4*)(f2 + (size_t)i2 * C2))[lane];
        const __half2* h0 = (const __half2*)&v0;
        const __half2* h1 = (const __half2*)&v1;
        const __half2* h2 = (const __half2*)&v2;
        uint4 ov;
        __half2* oh = (__half2*)&ov;
#pragma unroll
        for (int k = 0; k < 4; k++) {
            float2 a = __half22float2(h0[k]);
            float2 d = __half22float2(h1[k]);
            float2 e = __half22float2(h2[k]);
            oh[k] = __floats2half2_rn(w0 * a.x + w1 * d.x + w2 * e.x,
                                      w0 * a.y + w1 * d.y + w2 * e.y);
        }
        __half* x = g_X + (size_t)q * DIN;
        ((uint4*)x)[lane] = ov;

        float4 f = ((const float4*)(feat1 + (size_t)q * C1))[lane];
        __half2 f0 = __floats2half2_rn(f.x, f.y);
        __half2 f1h = __floats2half2_rn(f.z, f.w);
        *(__half2*)(x + C2 + lane * 4) = f0;
        *(__half2*)(x + C2 + lane * 4 + 2) = f1h;
    }
}

// ---------------------------------------------------------------------------
// Kernel B (R14): feat2 -> fp16 (8 elems/thread) AND W prep, one launch.
// ---------------------------------------------------------------------------
#define F2H_BLOCKS 2048
#define PREPW_BLOCKS 640

__global__ void prep_all(const float* __restrict__ feat2,
                         const float* __restrict__ W1,
                         const float* __restrict__ W2) {
    if (blockIdx.x < F2H_BLOCKS) {
        const size_t i = ((size_t)blockIdx.x * 256 + threadIdx.x) * 8;
        float4 v0 = *(const float4*)(feat2 + i);
        float4 v1 = *(const float4*)(feat2 + i + 4);
        __half2 h0 = __floats2half2_rn(v0.x, v0.y);
        __half2 h1 = __floats2half2_rn(v0.z, v0.w);
        __half2 h2 = __floats2half2_rn(v1.x, v1.y);
        __half2 h3 = __floats2half2_rn(v1.z, v1.w);
        uint4 o;
        o.x = *(const uint32_t*)&h0;
        o.y = *(const uint32_t*)&h1;
        o.z = *(const uint32_t*)&h2;
        o.w = *(const uint32_t*)&h3;
        *(uint4*)(g_feat2h + i) = o;
    } else {
        int i = (blockIdx.x - F2H_BLOCKS) * 256 + threadIdx.x;
        if (i < DIN * DOUT) {
            int k = i / DOUT, n = i % DOUT;
            g_W1T[n * DIN + k] = __float2half(W1[i]);
        } else {
            int j = i - DIN * DOUT;
            int k = j / DOUT, n = j % DOUT;
            g_W2T[n * DOUT + k] = __float2half(W2[j]);
        }
    }
}

// ---------------------------------------------------------------------------
// HGEMM1 persistent: 296 CTAs (2/SM, one wave). Each pins nblk = blk&1,
// loops 3-4 M-tiles; R8 3-stage cp.async ring continues ACROSS tiles
// (B chunks for the pinned nblk repeat per tile -> L1/L2 hits).
// Inner compute byte-identical to R8 per tile.
// ---------------------------------------------------------------------------
#define HGEMM_SMEM (3 * 32768)
#define G_GRID 296

__global__ __launch_bounds__(256, 2) void hgemm1_persist(
    const __half* __restrict__ A, const __half* __restrict__ Bt,
    const float* __restrict__ bias, __half* __restrict__ outH) {
    constexpr int K = DIN;
    constexpr int NC = K / 64;       // 6
    extern __shared__ char smem[];
    const uint32_t sb = smem_u32(smem);
    const int tid = threadIdx.x;
    const int w = tid >> 5, lane = tid & 31;
    const int wy = w >> 2, wx = w & 3;
    const int nblk = (blockIdx.x & 1) * 128;
    const int mbase = blockIdx.x >> 1;                 // 0..147
    const int ntiles = (512 - mbase + 147) / 148;      // 3 or 4
    const int total = ntiles * NC;

    const char* Bbase = (const char*)(Bt + (size_t)nblk * K);
    const int row_l = tid >> 3;
    const int ch_l = tid & 7;

    float acc[4][4][4];
#pragma unroll
    for (int i = 0; i < 4; i++)
#pragma unroll
        for (int j = 0; j < 4; j++)
#pragma unroll
            for (int k = 0; k < 4; k++) acc[i][j][k] = 0.0f;

    float bz[4][2];
#pragma unroll
    for (int nt = 0; nt < 4; nt++) {
        const int col = nblk + wx * 32 + nt * 8 + 2 * (lane & 3);
        bz[nt][0] = bias[col];
        bz[nt][1] = bias[col + 1];
    }

    auto issue = [&](int ct) {
        const int tile = ct / NC, c = ct % NC;
        const uint32_t base = sb + (uint32_t)(ct % 3) * 32768u;
        const char* ag = (const char*)(A + (size_t)(mbase + tile * 148) * 128 * K)
                       + (size_t)c * 128;
        const char* bg = Bbase + (size_t)c * 128;
#pragma unroll
        for (int rr = 0; rr < 4; rr++) {
            const int row = row_l + rr * 32;
            const uint32_t off = (uint32_t)(row * 128 + ch_l * 16);
            const uint32_t d = base + SWZ(off);
            CP_ASYNC16(d, ag + (size_t)row * (K * 2) + ch_l * 16);
            CP_ASYNC16(d + 16384, bg + (size_t)row * (K * 2) + ch_l * 16);
        }
        CP_COMMIT();
    };

    issue(0);
    issue(1);
    for (int ct = 0; ct < total; ct++) {
        if (ct + 1 < total) { CP_WAIT(1); } else { CP_WAIT(0); }
        __syncthreads();
        const uint32_t abase = sb + (uint32_t)(ct % 3) * 32768u;
        const uint32_t bbase = abase + 16384u;
#pragma unroll
        for (int ks = 0; ks < 4; ks++) {
            uint32_t af[4][4];
#pragma unroll
            for (int mt = 0; mt < 4; mt++) {
                const int row = wy * 64 + mt * 16 + ((lane >> 3) & 1) * 8 + (lane & 7);
                const int ch = ks * 2 + (lane >> 4);
                ldmatrix_x4(af[mt], abase + SWZ((uint32_t)(row * 128 + ch * 16)));
            }
            uint32_t bf[4][2];
#pragma unroll
            for (int p = 0; p < 2; p++) {
                const int t = lane >> 3;
                const int nrow = wx * 32 + (2 * p + (t >> 1)) * 8 + (lane & 7);
                const int ch = ks * 2 + (t & 1);
                uint32_t r[4];
                ldmatrix_x4(r, bbase + SWZ((uint32_t)(nrow * 128 + ch * 16)));
                bf[2 * p][0] = r[0]; bf[2 * p][1] = r[1];
                bf[2 * p + 1][0] = r[2]; bf[2 * p + 1][1] = r[3];
            }
#pragma unroll
            for (int mt = 0; mt < 4; mt++)
#pragma unroll
                for (int nt = 0; nt < 4; nt++)
                    mma16816(acc[mt][nt], af[mt], bf[nt]);
        }
        if (ct + 2 < total) issue(ct + 2);

        if (ct % NC == NC - 1) {
            const int mblk = (mbase + (ct / NC) * 148) * 128;
#pragma unroll
            for (int mt = 0; mt < 4; mt++) {
#pragma unroll
                for (int nt = 0; nt < 4; nt++) {
                    const int row0 = mblk + wy * 64 + mt * 16 + (lane >> 2);
                    const int col = nblk + wx * 32 + nt * 8 + 2 * (lane & 3);
                    float v00 = fmaxf(acc[mt][nt][0] + bz[nt][0], 0.0f);
                    float v01 = fmaxf(acc[mt][nt][1] + bz[nt][1], 0.0f);
                    float v10 = fmaxf(acc[mt][nt][2] + bz[nt][0], 0.0f);
                    float v11 = fmaxf(acc[mt][nt][3] + bz[nt][1], 0.0f);
                    *(__half2*)(outH + (size_t)row0 * 256 + col) = __floats2half2_rn(v00, v01);
                    *(__half2*)(outH + (size_t)(row0 + 8) * 256 + col) = __floats2half2_rn(v10, v11);
                    acc[mt][nt][0] = 0.0f; acc[mt][nt][1] = 0.0f;
                    acc[mt][nt][2] = 0.0f; acc[mt][nt][3] = 0.0f;
                }
            }
        }
    }
}

// ---------------------------------------------------------------------------
// HGEMM2 persistent (R15, proven): 296 CTAs, resident 64KB B, streamed A.
// ---------------------------------------------------------------------------
#define G2_SMEM (65536 + 3 * 16384)

__global__ __launch_bounds__(256, 2) void hgemm2_persist(
    const __half* __restrict__ A, const __half* __restrict__ Bt,
    const float* __restrict__ bias, float* __restrict__ outF) {
    extern __shared__ char smem[];
    const uint32_t sb = smem_u32(smem);
    const int tid = threadIdx.x;
    const int w = tid >> 5, lane = tid & 31;
    const int wy = w >> 2, wx = w & 3;
    const int nblk = (blockIdx.x & 1) * 128;
    const int mbase = blockIdx.x >> 1;
    const int ntiles = (512 - mbase + 147) / 148;
    const int total = ntiles * 4;

    const int row_l = tid >> 3;
    const int ch_l = tid & 7;

    float acc[4][4][4];
#pragma unroll
    for (int i = 0; i < 4; i++)
#pragma unroll
        for (int j = 0; j < 4; j++)
#pragma unroll
            for (int k = 0; k < 4; k++) acc[i][j][k] = 0.0f;

    float bz[4][2];
#pragma unroll
    for (int nt = 0; nt < 4; nt++) {
        const int col = nblk + wx * 32 + nt * 8 + 2 * (lane & 3);
        bz[nt][0] = bias[col];
        bz[nt][1] = bias[col + 1];
    }

    {
        const char* bg = (const char*)Bt;
#pragma unroll
        for (int r = 0; r < 16; r++) {
            const int idx = tid + r * 256;
            const int ck = idx >> 10;
            const int row = (idx >> 3) & 127;
            const int s = idx & 7;
            const uint32_t d = sb + (uint32_t)(ck * 16384)
                             + SWZ((uint32_t)(row * 128 + s * 16));
            CP_ASYNC16(d, bg + (size_t)(nblk + row) * 512 + ck * 128 + s * 16);
        }
    }

    auto issueA = [&](int ct) {
        const int tile = ct >> 2, c = ct & 3;
        const size_t mrow = (size_t)(mbase + tile * 148) * 128;
        const char* ag = (const char*)(A + mrow * 256) + c * 128;
        const uint32_t base = sb + 65536u + (uint32_t)(ct % 3) * 16384u;
#pragma unroll
        for (int rr = 0; rr < 4; rr++) {
            const int row = row_l + rr * 32;
            const uint32_t d = base + SWZ((uint32_t)(row * 128 + ch_l * 16));
            CP_ASYNC16(d, ag + (size_t)row * 512 + ch_l * 16);
        }
    };

    issueA(0); CP_COMMIT();
    issueA(1); CP_COMMIT();

    for (int ct = 0; ct < total; ct++) {
        if (ct + 1 < total) { CP_WAIT(1); } else { CP_WAIT(0); }
        __syncthreads();
        const uint32_t abase = sb + 65536u + (uint32_t)(ct % 3) * 16384u;
        const uint32_t bbase = sb + (uint32_t)((ct & 3) * 16384);
#pragma unroll
        for (int ks = 0; ks < 4; ks++) {
            uint32_t af[4][4];
#pragma unroll
            for (int mt = 0; mt < 4; mt++) {
                const int row = wy * 64 + mt * 16 + ((lane >> 3) & 1) * 8 + (lane & 7);
                const int ch = ks * 2 + (lane >> 4);
                ldmatrix_x4(af[mt], abase + SWZ((uint32_t)(row * 128 + ch * 16)));
            }
            uint32_t bf[4][2];
#pragma unroll
            for (int p = 0; p < 2; p++) {
                const int t = lane >> 3;
                const int nrow = wx * 32 + (2 * p + (t >> 1)) * 8 + (lane & 7);
                const int ch = ks * 2 + (t & 1);
                uint32_t r[4];
                ldmatrix_x4(r, bbase + SWZ((uint32_t)(nrow * 128 + ch * 16)));
                bf[2 * p][0] = r[0]; bf[2 * p][1] = r[1];
                bf[2 * p + 1][0] = r[2]; bf[2 * p + 1][1] = r[3];
            }
#pragma unroll
            for (int mt = 0; mt < 4; mt++)
#pragma unroll
                for (int nt = 0; nt < 4; nt++)
                    mma16816(acc[mt][nt], af[mt], bf[nt]);
        }
        if (ct + 2 < total) { issueA(ct + 2); CP_COMMIT(); }

        if ((ct & 3) == 3) {
            const int mblk = (mbase + (ct >> 2) * 148) * 128;
#pragma unroll
            for (int mt = 0; mt < 4; mt++) {
#pragma unroll
                for (int nt = 0; nt < 4; nt++) {
                    const int row0 = mblk + wy * 64 + mt * 16 + (lane >> 2);
                    const int col = nblk + wx * 32 + nt * 8 + 2 * (lane & 3);
                    float2 o0, o1;
                    o0.x = fmaxf(acc[mt][nt][0] + bz[nt][0], 0.0f);
                    o0.y = fmaxf(acc[mt][nt][1] + bz[nt][1], 0.0f);
                    o1.x = fmaxf(acc[mt][nt][2] + bz[nt][0], 0.0f);
                    o1.y = fmaxf(acc[mt][nt][3] + bz[nt][1], 0.0f);
                    *(float2*)(outF + (size_t)row0 * 256 + col) = o0;
                    *(float2*)(outF + (size_t)(row0 + 8) * 256 + col) = o1;
                    acc[mt][nt][0] = 0.0f; acc[mt][nt][1] = 0.0f;
                    acc[mt][nt][2] = 0.0f; acc[mt][nt][3] = 0.0f;
                }
            }
        }
    }
}

// ---------------------------------------------------------------------------
extern "C" void kernel_launch(void* const* d_in, const int* in_sizes, int n_in,
                              void* d_out, int out_size) {
    const float* xyz1  = (const float*)d_in[0];
    const float* feat1 = (const float*)d_in[1];
    const float* xyz2  = (const float*)d_in[2];
    const float* feat2 = (const float*)d_in[3];
    const float* W1    = (const float*)d_in[4];
    const float* b1    = (const float*)d_in[5];
    const float* W2    = (const float*)d_in[6];
    const float* b2    = (const float*)d_in[7];
    float* out = (float*)d_out;

    __half *X, *H, *W1T, *W2T;
    cudaGetSymbolAddress((void**)&X, g_X);
    cudaGetSymbolAddress((void**)&H, g_H);
    cudaGetSymbolAddress((void**)&W1T, g_W1T);
    cudaGetSymbolAddress((void**)&W2T, g_W2T);

    cudaFuncSetAttribute((const void*)hgemm1_persist,
                         cudaFuncAttributeMaxDynamicSharedMemorySize, HGEMM_SMEM);
    cudaFuncSetAttribute((const void*)hgemm2_persist,
                         cudaFuncAttributeMaxDynamicSharedMemorySize, G2_SMEM);

    prep_all<<<F2H_BLOCKS + PREPW_BLOCKS, 256>>>(feat2, W1, W2);
    knn_interp_kernel<<<NQ / 64, 256>>>(xyz1, xyz2, feat1);

    hgemm1_persist<<<G_GRID, 256, HGEMM_SMEM>>>(X, W1T, b1, H);
    hgemm2_persist<<<G_GRID, 256, G2_SMEM>>>(H, W2T, b2, out);
}